// round 15
// baseline (speedup 1.0000x reference)
#include <cuda_runtime.h>
#include <cuda_fp16.h>
#include <cstdint>

#define Bb 8
#define Nn 4096
#define Mm 1024
#define LOG2E 1.4426950408889634f

// ---------------------------------------------------------------------------
// Scratch (device globals) — pre-swizzled images for flat bulk copies
// ---------------------------------------------------------------------------
__device__ __half g_qh[Bb*Nn*64];    // Q hi fp16 (x log2e), per-64-row-chunk images
__device__ __half g_ql[Bb*Nn*64];    // Q lo fp16
__device__ __half g_kh[Bb*Mm*64];    // K hi fp16 ([key][d])
__device__ __half g_kl[Bb*Mm*64];    // K lo fp16
__device__ __half g_qaug[Bb*Nn*24];  // Q-side RBF aug rows (x log2e)
__device__ __half g_kaug[Bb*Mm*24];  // K-side RBF aug rows
__device__ __half g_vT[Bb*Mm*64];    // V^T fp16 images ([d][key])
__device__ __half g_woh[128*128];    // Wo^T hi image
__device__ __half g_wol[128*128];    // Wo^T lo image

#define TH2 (-4.32192809489f)        // log2(0.05)

// ---------------------------------------------------------------------------
// Helpers
// ---------------------------------------------------------------------------
__device__ __forceinline__ uint32_t smem_u32(const void* p) {
    uint32_t a;
    asm("{ .reg .u64 t; cvta.to.shared.u64 t, %1; cvt.u32.u64 %0, t; }" : "=r"(a) : "l"(p));
    return a;
}
__device__ __forceinline__ float ex2f(float x) {
    float y;
    asm("ex2.approx.ftz.f32 %0, %1;" : "=f"(y) : "f"(x));
    return y;
}
__device__ __forceinline__ uint32_t elect_one() {
    uint32_t p;
    asm volatile("{ .reg .pred p; elect.sync _|p, 0xFFFFFFFF; selp.b32 %0,1,0,p; }" : "=r"(p));
    return p;
}

#define MBAR_INIT(a, c) asm volatile("mbarrier.init.shared.b64 [%0], %1;" :: "r"(a), "r"((uint32_t)(c)) : "memory")
#define MBAR_EXPECT(a, b) asm volatile("mbarrier.arrive.expect_tx.shared.b64 _, [%0], %1;" :: "r"(a), "r"((uint32_t)(b)) : "memory")
#define MBAR_ARRIVE(a) asm volatile("mbarrier.arrive.shared.b64 _, [%0];" :: "r"(a) : "memory")
#define MBAR_WAIT(a, ph) do { \
    asm volatile("{ .reg .pred P1; WL_%=: mbarrier.try_wait.parity.acquire.cta.shared::cta.b64 P1, [%0], %1, 0x989680; @P1 bra.uni WD_%=; bra.uni WL_%=; WD_%=: }" \
        :: "r"(a), "r"((uint32_t)(ph)) : "memory"); } while (0)

__device__ __forceinline__ void bulk_cp(uint32_t dst, const void* src, uint32_t bytes, uint32_t mbar) {
    asm volatile("cp.async.bulk.shared::cta.global.mbarrier::complete_tx::bytes [%0], [%1], %2, [%3];"
        :: "r"(dst), "l"(src), "r"(bytes), "r"(mbar) : "memory");
}

__device__ __forceinline__ void ldsm4(uint32_t r[4], uint32_t a) {
    asm volatile("ldmatrix.sync.aligned.m8n8.x4.shared.b16 {%0,%1,%2,%3}, [%4];"
        : "=r"(r[0]), "=r"(r[1]), "=r"(r[2]), "=r"(r[3]) : "r"(a));
}

__device__ __forceinline__ void mma_f16(float c[4], const uint32_t a[4], const uint32_t b[2]) {
    asm volatile("mma.sync.aligned.m16n8k16.row.col.f32.f16.f16.f32 "
        "{%0,%1,%2,%3}, {%4,%5,%6,%7}, {%8,%9}, {%0,%1,%2,%3};"
        : "+f"(c[0]), "+f"(c[1]), "+f"(c[2]), "+f"(c[3])
        : "r"(a[0]), "r"(a[1]), "r"(a[2]), "r"(a[3]), "r"(b[0]), "r"(b[1]));
}

// ---------------------------------------------------------------------------
// prep_proj: ONE wide launch (944 blocks). (UNCHANGED from R14)
// ---------------------------------------------------------------------------
#define PA_H 0u
#define PA_L 8192u
#define PW_H 16384u
#define PW_L 24576u

__global__ __launch_bounds__(256) void prep_proj_kernel(
    const float* __restrict__ xyz1, const float* __restrict__ xyz2,
    const float* __restrict__ gammap,
    const float* __restrict__ p1, const float* __restrict__ p2,
    const float* __restrict__ Wq, const float* __restrict__ Wk,
    const float* __restrict__ Wv, const float* __restrict__ Wo)
{
    __shared__ __align__(16) char sm[32768];
    int bx = blockIdx.x;
    int tid = threadIdx.x;

    if (bx >= 928) {
        int base = (bx - 928) * 1024;
#pragma unroll
        for (int it = 0; it < 4; it++) {
            int i = base + tid + 256*it;
            int k = i >> 7, c = i & 127;
            float w = Wo[i];
            __half h = __float2half_rn(w);
            __half l = __float2half_rn(w - __half2float(h));
            uint32_t sw = ((uint32_t)(k >> 3)) ^ (uint32_t)(c & 7);
            uint32_t off = (uint32_t)c*128u + sw*8u + (uint32_t)(k & 7);
            g_woh[off] = h; g_wol[off] = l;
        }
        return;
    }
    if (bx >= 768) {
        int gr = (bx - 768) * 256 + tid;
        float g = gammap[0];
        float v[5];
        __half* dst;
        bool qside = gr < Bb*Nn;
        if (qside) {
            int b = gr >> 12, n = gr & (Nn-1);
            const float* xp = xyz1 + (size_t)gr*3;
            float x = xp[0], y = xp[1], z = xp[2];
            float gl = g * LOG2E;
            v[0] = 2.0f*gl*x; v[1] = 2.0f*gl*y; v[2] = 2.0f*gl*z;
            v[3] = -gl*(x*x + y*y + z*z); v[4] = LOG2E;
            int img = b*64 + (n >> 6), rr = n & 63;
            dst = g_qaug + (size_t)img*1536 + rr*24;
        } else {
            int gr2 = gr - Bb*Nn;
            if (gr2 >= Bb*Mm) return;
            int b = gr2 >> 10, m = gr2 & (Mm-1);
            const float* xp = xyz2 + (size_t)gr2*3;
            float x = xp[0], y = xp[1], z = xp[2];
            v[0] = x; v[1] = y; v[2] = z;
            v[3] = 1.0f; v[4] = -g*(x*x + y*y + z*z);
            int img = b*16 + (m >> 6), rr = m & 63;
            dst = g_kaug + (size_t)img*1536 + rr*24;
        }
        __half h[5], l[5];
#pragma unroll
        for (int i = 0; i < 5; i++) {
            h[i] = __float2half_rn(v[i]);
            l[i] = __float2half_rn(v[i] - __half2float(h[i]));
        }
        __half row[24];
#pragma unroll
        for (int i = 0; i < 24; i++) row[i] = __float2half_rn(0.0f);
#pragma unroll
        for (int i = 0; i < 5; i++) {
            row[i] = h[i];
            if (qside) { row[5+i] = l[i]; row[10+i] = h[i]; }
            else       { row[5+i] = h[i]; row[10+i] = l[i]; }
        }
        float4* d4 = (float4*)dst;
        const float4* s4 = (const float4*)row;
        d4[0] = s4[0]; d4[1] = s4[1]; d4[2] = s4[2];
        return;
    }

    uint32_t sb = smem_u32(sm);
    int lane = tid & 31, wid = tid >> 5;
    int wm = wid & 3, wn = wid >> 2;

    int mode, rowbase;
    const float *A, *W;
    if (bx < 512)      { mode = 0; A = p1; W = Wq; rowbase = bx*64; }
    else if (bx < 640) { mode = 1; A = p2; W = Wk; rowbase = (bx-512)*64; }
    else               { mode = 2; A = p2; W = Wv; rowbase = (bx-640)*64; }

#pragma unroll
    for (int i = 0; i < 4; i++) {
        int lin = tid + 256*i;
        int r = lin >> 4;
        int k = (lin & 15) * 4;
        float4 v = *(const float4*)(A + (size_t)(rowbase + r)*64 + k);
        __half h[4], l[4];
        h[0]=__float2half_rn(v.x); l[0]=__float2half_rn(v.x-__half2float(h[0]));
        h[1]=__float2half_rn(v.y); l[1]=__float2half_rn(v.y-__half2float(h[1]));
        h[2]=__float2half_rn(v.z); l[2]=__float2half_rn(v.z-__half2float(h[2]));
        h[3]=__float2half_rn(v.w); l[3]=__float2half_rn(v.w-__half2float(h[3]));
        uint32_t off = (uint32_t)r*64u + ((((uint32_t)k >> 3) ^ (uint32_t)(r & 7)) << 3) + (uint32_t)(k & 7);
        *(__half2*)(sm + PA_H + off*2)     = __halves2half2(h[0], h[1]);
        *(__half2*)(sm + PA_H + off*2 + 4) = __halves2half2(h[2], h[3]);
        *(__half2*)(sm + PA_L + off*2)     = __halves2half2(l[0], l[1]);
        *(__half2*)(sm + PA_L + off*2 + 4) = __halves2half2(l[2], l[3]);
    }
#pragma unroll
    for (int it = 0; it < 16; it++) {
        int i = tid + 256*it;
        int k = i >> 6, n = i & 63;
        float w = W[i];
        __half h = __float2half_rn(w);
        __half l = __float2half_rn(w - __half2float(h));
        uint32_t off = (uint32_t)n*64u + ((((uint32_t)k >> 3) ^ (uint32_t)(n & 7)) << 3) + (uint32_t)(k & 7);
        *(__half*)(sm + PW_H + off*2) = h;
        *(__half*)(sm + PW_L + off*2) = l;
    }
    __syncthreads();

    uint32_t frowA = (uint32_t)((lane & 7) + (((lane >> 3) & 1) << 3));
    uint32_t fchkA = (uint32_t)(lane >> 4);
    uint32_t frowB = (uint32_t)((lane & 7) + ((lane >> 4) << 3));
    uint32_t fchkB = (uint32_t)((lane >> 3) & 1);
    uint32_t fsw   = (uint32_t)(lane & 7);

    uint32_t arow = (uint32_t)(wm*16) + frowA;
    uint32_t brow0 = (uint32_t)(wn*32) + frowB;

    float acc[4][4] = {};
#pragma unroll
    for (int s = 0; s < 4; s++) {
        uint32_t chA = ((uint32_t)(2*s) + fchkA) ^ fsw;
        uint32_t chB = ((uint32_t)(2*s) + fchkB) ^ fsw;
        uint32_t ah[4], al[4], bh[2][4], bl[2][4];
        ldsm4(ah, sb + PA_H + arow*128u + (chA << 4));
        ldsm4(al, sb + PA_L + arow*128u + (chA << 4));
        ldsm4(bh[0], sb + PW_H + brow0*128u + (chB << 4));
        ldsm4(bh[1], sb + PW_H + (brow0 + 16u)*128u + (chB << 4));
        ldsm4(bl[0], sb + PW_L + brow0*128u + (chB << 4));
        ldsm4(bl[1], sb + PW_L + (brow0 + 16u)*128u + (chB << 4));
#pragma unroll
        for (int fn = 0; fn < 4; fn++) {
            mma_f16(acc[fn], ah, &bh[fn>>1][2*(fn&1)]);
            mma_f16(acc[fn], al, &bh[fn>>1][2*(fn&1)]);
            mma_f16(acc[fn], ah, &bl[fn>>1][2*(fn&1)]);
        }
    }
    __syncthreads();

    int jj = lane & 3;
    int r0 = wm*16 + (lane >> 2);
    if (mode <= 1) {
        float scl = (mode == 0) ? LOG2E : 1.0f;
#pragma unroll
        for (int fn = 0; fn < 4; fn++) {
            int col = wn*32 + fn*8 + 2*jj;
#pragma unroll
            for (int hh = 0; hh < 2; hh++) {
                int r = r0 + 8*hh;
                float c0 = acc[fn][2*hh+0]*scl, c1 = acc[fn][2*hh+1]*scl;
                __half h0 = __float2half_rn(c0), h1 = __float2half_rn(c1);
                __half l0 = __float2half_rn(c0 - __half2float(h0));
                __half l1 = __float2half_rn(c1 - __half2float(h1));
                uint32_t off = (uint32_t)r*64u + ((((uint32_t)col >> 3) ^ (uint32_t)(r & 7)) << 3) + (uint32_t)(col & 7);
                *(__half2*)(sm + off*2)         = __halves2half2(h0, h1);
                *(__half2*)(sm + 8192 + off*2)  = __halves2half2(l0, l1);
            }
        }
        __syncthreads();
        int img = (mode == 0) ? bx : bx - 512;
        __half* dh = (mode == 0 ? g_qh : g_kh) + (size_t)img*4096;
        __half* dl = (mode == 0 ? g_ql : g_kl) + (size_t)img*4096;
#pragma unroll
        for (int i = 0; i < 2; i++) {
            int lin = tid + 256*i;
            *(uint4*)((char*)dh + lin*16) = *(const uint4*)(sm + lin*16);
            *(uint4*)((char*)dl + lin*16) = *(const uint4*)(sm + 8192 + lin*16);
        }
    } else {
        __half* st = (__half*)sm;
#pragma unroll
        for (int fn = 0; fn < 4; fn++) {
            int col = wn*32 + fn*8 + 2*jj;
#pragma unroll
            for (int hh = 0; hh < 2; hh++) {
                int kk = r0 + 8*hh;
#pragma unroll
                for (int j = 0; j < 2; j++) {
                    int e = col + j;
                    uint32_t off = (uint32_t)e*64u + ((((uint32_t)kk >> 3) ^ (uint32_t)(e & 7)) << 3) + (uint32_t)(kk & 7);
                    st[off] = __float2half_rn(acc[fn][2*hh+j]);
                }
            }
        }
        __syncthreads();
        __half* dv = g_vT + (size_t)(bx - 640)*4096;
#pragma unroll
        for (int i = 0; i < 2; i++) {
            int lin = tid + 256*i;
            *(uint4*)((char*)dv + lin*16) = *(const uint4*)(sm + lin*16);
        }
    }
}

// ---------------------------------------------------------------------------
// Fused attention + OUTPUT MLP. THREE-stage pipelined buffers (prefetch
// distance 3); log2-domain exp, predicated RBF exp, operand-swapped MMA2,
// flash row-max, merged single-pass tail MLP.
// ---------------------------------------------------------------------------
#define SM_QH     0u
#define SM_QL     8192u
#define SM_QAUG   16384u
#define SM_BUF0   19456u
#define BUF_KH    0u
#define BUF_KL    8192u
#define BUF_KAUG  16384u
#define BUF_V     19456u
#define BUF_BYTES 27648u
#define RED_STRIDE 68
#define TL_AH   0u
#define TL_AL   16384u
#define TL_BH   32768u
#define TL_BL   65536u
#define TL_RED  65536u       // overlaps TL_BL; BL copied after combine reads RED
#define SM_TOTAL 102400      // SM_BUF0 + 3*BUF_BYTES (tail needs 98304)

__global__ __launch_bounds__(256, 2) void attn_mma_kernel(
    const float* __restrict__ p1, const float* __restrict__ bo,
    float* __restrict__ out)
{
    extern __shared__ char dyn[];
    __shared__ __align__(8) uint64_t mbars[6];   // full0..2, free0..2
    __shared__ float sDen[2][64];
    __shared__ float sM[2][64];

    uint32_t sb = smem_u32(dyn);
    int tid = threadIdx.x, lane = tid & 31, wid = tid >> 5;
    int wm = wid & 3, wn = wid >> 2;
    int bI = blockIdx.y, nbase = blockIdx.x * 64;

    uint32_t mb[3] = { smem_u32(&mbars[0]), smem_u32(&mbars[1]), smem_u32(&mbars[2]) };
    uint32_t fr[3] = { smem_u32(&mbars[3]), smem_u32(&mbars[4]), smem_u32(&mbars[5]) };
    if (tid == 0) {
#pragma unroll
        for (int i = 0; i < 3; i++) { MBAR_INIT(mb[i], 1); MBAR_INIT(fr[i], 8); }
    }
    __syncthreads();

    if (tid == 0) {
        int img = bI * 16;
        int qimg = bI*64 + blockIdx.x;
        MBAR_EXPECT(mb[0], 8192u*2 + 3072u + BUF_BYTES);
        bulk_cp(sb + SM_QH,   g_qh   + (size_t)qimg*4096, 8192, mb[0]);
        bulk_cp(sb + SM_QL,   g_ql   + (size_t)qimg*4096, 8192, mb[0]);
        bulk_cp(sb + SM_QAUG, g_qaug + (size_t)qimg*1536, 3072, mb[0]);
        bulk_cp(sb + SM_BUF0 + BUF_KH,   g_kh   + (size_t)img*4096, 8192, mb[0]);
        bulk_cp(sb + SM_BUF0 + BUF_KL,   g_kl   + (size_t)img*4096, 8192, mb[0]);
        bulk_cp(sb + SM_BUF0 + BUF_KAUG, g_kaug + (size_t)img*1536, 3072, mb[0]);
        bulk_cp(sb + SM_BUF0 + BUF_V,    g_vT   + (size_t)img*4096, 8192, mb[0]);
#pragma unroll
        for (int q = 1; q < 3; q++) {
            uint32_t dstb = sb + SM_BUF0 + (uint32_t)q*BUF_BYTES;
            MBAR_EXPECT(mb[q], BUF_BYTES);
            bulk_cp(dstb + BUF_KH,   g_kh   + (size_t)(img+q)*4096, 8192, mb[q]);
            bulk_cp(dstb + BUF_KL,   g_kl   + (size_t)(img+q)*4096, 8192, mb[q]);
            bulk_cp(dstb + BUF_KAUG, g_kaug + (size_t)(img+q)*1536, 3072, mb[q]);
            bulk_cp(dstb + BUF_V,    g_vT   + (size_t)(img+q)*4096, 8192, mb[q]);
        }
    }

    uint32_t frowA = (uint32_t)((lane & 7) + (((lane >> 3) & 1) << 3));
    uint32_t fchkA = (uint32_t)(lane >> 4);
    uint32_t frowB = (uint32_t)((lane & 7) + ((lane >> 4) << 3));
    uint32_t fchkB = (uint32_t)((lane >> 3) & 1);
    uint32_t fsw   = (uint32_t)(lane & 7);
    int jj = lane & 3;

    MBAR_WAIT(mb[0], 0);
    uint32_t qaug[4];
    ldsm4(qaug, sb + SM_QAUG + ((uint32_t)(wm*16) + frowA)*48u + fchkA*16u);

    float oaccT[4][2][4] = {};
    float dsum[2] = {};
    float mold[2] = { -1e30f, -1e30f };

    uint32_t qrow = (uint32_t)(wm*16) + frowA;
    uint32_t krow0 = (uint32_t)(wn*32) + frowB;

    int bcur = 0;    // t % 3
    for (int t = 0; t < 16; t++) {
        int par = (t * 0x5556) >> 16;          // t/3 (t<16)
        par &= 1;
        uint32_t bufb = sb + SM_BUF0 + (uint32_t)bcur*BUF_BYTES;
        if (t) MBAR_WAIT(mb[bcur], par);

        // ---- MMA1: S' (log2 domain, 3-pass fp16) + R' (aug) ----
        float sacc[4][4] = {};
        float racc[4][4] = {};
#pragma unroll
        for (int s = 0; s < 4; s++) {
            uint32_t chA = ((uint32_t)(2*s) + fchkA) ^ fsw;
            uint32_t chB = ((uint32_t)(2*s) + fchkB) ^ fsw;
            uint32_t qh_f[4], ql_f[4], kh2[2][4], kl2[2][4];
            ldsm4(qh_f, sb + SM_QH + qrow*128u + (chA << 4));
            ldsm4(ql_f, sb + SM_QL + qrow*128u + (chA << 4));
            ldsm4(kh2[0], bufb + BUF_KH + krow0*128u + (chB << 4));
            ldsm4(kh2[1], bufb + BUF_KH + (krow0 + 16u)*128u + (chB << 4));
            ldsm4(kl2[0], bufb + BUF_KL + krow0*128u + (chB << 4));
            ldsm4(kl2[1], bufb + BUF_KL + (krow0 + 16u)*128u + (chB << 4));
#pragma unroll
            for (int fn = 0; fn < 4; fn++) {
                mma_f16(sacc[fn], qh_f, &kh2[fn>>1][2*(fn&1)]);
                mma_f16(sacc[fn], qh_f, &kl2[fn>>1][2*(fn&1)]);
                mma_f16(sacc[fn], ql_f, &kh2[fn>>1][2*(fn&1)]);
            }
        }
        {
            uint32_t ka[2][4];
            ldsm4(ka[0], bufb + BUF_KAUG + krow0*48u + fchkB*16u);
            ldsm4(ka[1], bufb + BUF_KAUG + (krow0 + 16u)*48u + fchkB*16u);
#pragma unroll
            for (int fn = 0; fn < 4; fn++)
                mma_f16(racc[fn], qaug, &ka[fn>>1][2*(fn&1)]);
        }

        // ---- flash row-max update (log2 units) ----
        float mt0 = sacc[0][0], mt1 = sacc[0][2];
#pragma unroll
        for (int fn = 0; fn < 4; fn++) {
            mt0 = fmaxf(mt0, fmaxf(sacc[fn][0], sacc[fn][1]));
            mt1 = fmaxf(mt1, fmaxf(sacc[fn][2], sacc[fn][3]));
        }
        mt0 = fmaxf(mt0, __shfl_xor_sync(0xFFFFFFFFu, mt0, 1));
        mt0 = fmaxf(mt0, __shfl_xor_sync(0xFFFFFFFFu, mt0, 2));
        mt1 = fmaxf(mt1, __shfl_xor_sync(0xFFFFFFFFu, mt1, 1));
        mt1 = fmaxf(mt1, __shfl_xor_sync(0xFFFFFFFFu, mt1, 2));
        float mn0 = fmaxf(mold[0], mt0);
        float mn1 = fmaxf(mold[1], mt1);
        bool ch = (mn0 > mold[0]) || (mn1 > mold[1]);
        if (__ballot_sync(0xFFFFFFFFu, ch)) {
            float f0 = ex2f(mold[0] - mn0);
            float f1 = ex2f(mold[1] - mn1);
            dsum[0] *= f0; dsum[1] *= f1;
            float fq0 = __shfl_sync(0xFFFFFFFFu, f0, 8*jj);
            float fq1 = __shfl_sync(0xFFFFFFFFu, f0, 8*jj + 4);
            float fq2 = __shfl_sync(0xFFFFFFFFu, f1, 8*jj);
            float fq3 = __shfl_sync(0xFFFFFFFFu, f1, 8*jj + 4);
#pragma unroll
            for (int g = 0; g < 4; g++) {
                oaccT[g][0][0] *= fq0; oaccT[g][0][1] *= fq1;
                oaccT[g][0][2] *= fq0; oaccT[g][0][3] *= fq1;
                oaccT[g][1][0] *= fq2; oaccT[g][1][1] *= fq3;
                oaccT[g][1][2] *= fq2; oaccT[g][1][3] *= fq3;
            }
        }
        mold[0] = mn0; mold[1] = mn1;

        // ---- epilogue: e2 = 2^(s'-m'), u = 2^(r') predicated, pv = e2*u ----
        uint32_t bq[2][2][2];
#pragma unroll
        for (int kc = 0; kc < 2; kc++) {
#pragma unroll
            for (int fo = 0; fo < 2; fo++) {
                int fn = 2*kc + fo;
                float pvf[4];
#pragma unroll
                for (int e = 0; e < 4; e++) {
                    float s = sacc[fn][e];
                    float m = (e < 2) ? mn0 : mn1;
                    float e2 = ex2f(s - m);
                    if (e < 2) dsum[0] += e2; else dsum[1] += e2;
                    float r = racc[fn][e];
                    float u = 0.0f;
                    if (r > TH2) u = ex2f(r);
                    pvf[e] = e2 * u;
                }
                __half2 p01 = __floats2half2_rn(pvf[0], pvf[1]);
                __half2 p23 = __floats2half2_rn(pvf[2], pvf[3]);
                bq[kc][0][fo] = *(uint32_t*)&p01;
                bq[kc][1][fo] = *(uint32_t*)&p23;
            }
        }

        // ---- MMA2: O^T += V^T x P^T (fp16) ----
#pragma unroll
        for (int kc = 0; kc < 2; kc++) {
            uint32_t chV = ((uint32_t)(wn*4 + 2*kc) + fchkA) ^ fsw;
#pragma unroll
            for (int g = 0; g < 4; g++) {
                uint32_t vfr[4];
                ldsm4(vfr, bufb + BUF_V + ((uint32_t)(16*g) + frowA)*128u + (chV << 4));
                mma_f16(oaccT[g][0], vfr, bq[kc][0]);
                mma_f16(oaccT[g][1], vfr, bq[kc][1]);
            }
        }

        if (elect_one()) MBAR_ARRIVE(fr[bcur]);

        if (t <= 12 && tid == 0) {
            MBAR_WAIT(fr[bcur], par);
            int img = bI*16 + t + 3;
            MBAR_EXPECT(mb[bcur], BUF_BYTES);
            bulk_cp(bufb + BUF_KH,   g_kh   + (size_t)img*4096, 8192, mb[bcur]);
            bulk_cp(bufb + BUF_KL,   g_kl   + (size_t)img*4096, 8192, mb[bcur]);
            bulk_cp(bufb + BUF_KAUG, g_kaug + (size_t)img*1536, 3072, mb[bcur]);
            bulk_cp(bufb + BUF_V,    g_vT   + (size_t)img*4096, 8192, mb[bcur]);
        }
        bcur = (bcur == 2) ? 0 : bcur + 1;
    }

    __syncthreads();

    // =======================  TAIL: combine + fused MLP  ====================

#pragma unroll
    for (int off = 1; off < 4; off <<= 1)
#pragma unroll
        for (int h = 0; h < 2; h++)
            dsum[h] += __shfl_xor_sync(0xFFFFFFFFu, dsum[h], off);
    int rloc = lane >> 2;
    if (jj == 0) {
#pragma unroll
        for (int h = 0; h < 2; h++) {
            sDen[wn][wm*16 + rloc + 8*h] = dsum[h];
            sM[wn][wm*16 + rloc + 8*h]   = mold[h];
        }
    }

    float* sRed = (float*)(dyn + TL_RED);
    if (wn == 1) {
#pragma unroll
        for (int g = 0; g < 4; g++)
#pragma unroll
            for (int qb = 0; qb < 2; qb++) {
                int q0 = wm*16 + qb*8 + 2*jj;
                int d0 = 16*g + rloc;
                sRed[(q0+0)*RED_STRIDE + d0]     = oaccT[g][qb][0];
                sRed[(q0+1)*RED_STRIDE + d0]     = oaccT[g][qb][1];
                sRed[(q0+0)*RED_STRIDE + d0 + 8] = oaccT[g][qb][2];
                sRed[(q0+1)*RED_STRIDE + d0 + 8] = oaccT[g][qb][3];
            }
    }

    // A image p1-half (all warps) + Wo^T hi copy
    {
        const float* p1base = p1 + ((size_t)bI*Nn + nbase)*64;
#pragma unroll
        for (int i = 0; i < 4; i++) {
            int lin = tid + 256*i;
            int r = lin >> 4;
            int k = (lin & 15) * 4;
            float4 v = *(const float4*)(p1base + (size_t)r*64 + k);
            __half h[4], l[4];
            h[0]=__float2half_rn(v.x); l[0]=__float2half_rn(v.x-__half2float(h[0]));
            h[1]=__float2half_rn(v.y); l[1]=__float2half_rn(v.y-__half2float(h[1]));
            h[2]=__float2half_rn(v.z); l[2]=__float2half_rn(v.z-__half2float(h[2]));
            h[3]=__float2half_rn(v.w); l[3]=__float2half_rn(v.w-__half2float(h[3]));
            uint32_t sw = ((uint32_t)(k >> 3)) ^ (uint32_t)(r & 7);
            uint32_t off = (uint32_t)r*128u + sw*8u + (uint32_t)(k & 7);
            *(__half2*)(dyn + TL_AH + off*2)     = __halves2half2(h[0], h[1]);
            *(__half2*)(dyn + TL_AH + off*2 + 4) = __halves2half2(h[2], h[3]);
            *(__half2*)(dyn + TL_AL + off*2)     = __halves2half2(l[0], l[1]);
            *(__half2*)(dyn + TL_AL + off*2 + 4) = __halves2half2(l[2], l[3]);
        }
    }
#pragma unroll
    for (int i = 0; i < 8; i++) {
        int lin = tid + 256*i;
        *(uint4*)(dyn + TL_BH + lin*16) = *(const uint4*)((const char*)g_woh + lin*16);
    }
    __syncthreads();

    // wn==0: combine halves (log2-domain maxes), write kern cols 64..127
    if (wn == 0) {
        float ca[2][2], cb[2][2];
#pragma unroll
        for (int qb = 0; qb < 2; qb++)
#pragma unroll
            for (int par2 = 0; par2 < 2; par2++) {
                int rg = wm*16 + qb*8 + 2*jj + par2;
                float m0 = sM[0][rg], m1 = sM[1][rg];
                float Mx = fmaxf(m0, m1);
                float e0 = ex2f(m0 - Mx), e1 = ex2f(m1 - Mx);
                float den = sDen[0][rg]*e0 + sDen[1][rg]*e1;
                float inv = 1.0f / den;
                ca[qb][par2] = e0 * inv;
                cb[qb][par2] = e1 * inv;
            }
#pragma unroll
        for (int g = 0; g < 4; g++)
#pragma unroll
            for (int qb = 0; qb < 2; qb++) {
                int q0 = wm*16 + qb*8 + 2*jj;
                int d0 = 16*g + rloc;
#pragma unroll
                for (int e = 0; e < 4; e++) {
                    int par2 = e & 1;
                    int r = q0 + par2;
                    int d = d0 + 8*(e >> 1);
                    float val = oaccT[g][qb][e]*ca[qb][par2]
                              + sRed[r*RED_STRIDE + d]*cb[qb][par2];
                    int k = 64 + d;
                    __half h = __float2half_rn(val);
                    __half l = __float2half_rn(val - __half2float(h));
                    uint32_t sw = ((uint32_t)(k >> 3)) ^ (uint32_t)(r & 7);
                    uint32_t off = (uint32_t)r*128u + sw*8u + (uint32_t)(k & 7);
                    *(__half*)(dyn + TL_AH + off*2) = h;
                    *(__half*)(dyn + TL_AL + off*2) = l;
                }
            }
    }
    __syncthreads();

    // Wo^T lo copy (over RED — safe now)
#pragma unroll
    for (int i = 0; i < 8; i++) {
        int lin = tid + 256*i;
        *(uint4*)(dyn + TL_BL + lin*16) = *(const uint4*)((const char*)g_wol + lin*16);
    }
    __syncthreads();

    // merged single-pass MLP: ah*bh + al*bh + ah*bl
    uint32_t arow = (uint32_t)(wm*16) + frowA;
    uint32_t brow0 = (uint32_t)(wn*64) + frowB;
    float macc[8][4] = {};
#pragma unroll
    for (int s = 0; s < 8; s++) {
        uint32_t chA = ((uint32_t)(2*s) + fchkA) ^ fsw;
        uint32_t chB = ((uint32_t)(2*s) + fchkB) ^ fsw;
        uint32_t ah[4], al[4], bh[4][4], bl[4][4];
        ldsm4(ah, sb + TL_AH + arow*256u + (chA << 4));
        ldsm4(al, sb + TL_AL + arow*256u + (chA << 4));
#pragma unroll
        for (int g = 0; g < 4; g++) {
            ldsm4(bh[g], sb + TL_BH + (brow0 + 16u*g)*256u + (chB << 4));
            ldsm4(bl[g], sb + TL_BL + (brow0 + 16u*g)*256u + (chB << 4));
        }
#pragma unroll
        for (int fn = 0; fn < 8; fn++) {
            mma_f16(macc[fn], ah, &bh[fn>>1][2*(fn&1)]);
            mma_f16(macc[fn], al, &bh[fn>>1][2*(fn&1)]);
            mma_f16(macc[fn], ah, &bl[fn>>1][2*(fn&1)]);
        }
    }

    // bias + relu + store
#pragma unroll
    for (int fn = 0; fn < 8; fn++) {
        int col = wn*64 + fn*8 + 2*jj;
        float2 bv = *(const float2*)(bo + col);
#pragma unroll
        for (int h = 0; h < 2; h++) {
            int grow = bI*Nn + nbase + wm*16 + rloc + 8*h;
            float2 o;
            o.x = fmaxf(macc[fn][2*h+0] + bv.x, 0.0f);
            o.y = fmaxf(macc[fn][2*h+1] + bv.y, 0.0f);
            *(float2*)(out + (size_t)grow*128 + col) = o;
        }
    }
}

// ---------------------------------------------------------------------------
extern "C" void kernel_launch(void* const* d_in, const int* in_sizes, int n_in,
                              void* d_out, int out_size)
{
    const float* xyz1 = (const float*)d_in[0];
    const float* xyz2 = (const float*)d_in[1];
    const float* p1   = (const float*)d_in[2];
    const float* p2   = (const float*)d_in[3];
    const float* Wq   = (const float*)d_in[4];
    const float* Wk   = (const float*)d_in[5];
    const float* Wv   = (const float*)d_in[6];
    const float* gm   = (const float*)d_in[7];
    const float* Wo   = (const float*)d_in[8];
    const float* bo   = (const float*)d_in[9];
    float* out = (float*)d_out;

    prep_proj_kernel<<<944, 256>>>(xyz1, xyz2, gm, p1, p2, Wq, Wk, Wv, Wo);

    cudaFuncSetAttribute(attn_mma_kernel, cudaFuncAttributeMaxDynamicSharedMemorySize, SM_TOTAL);
    attn_mma_kernel<<<dim3(Nn/64, Bb), 256, SM_TOTAL>>>(p1, bo, out);
}

// round 17
// speedup vs baseline: 1.0269x; 1.0269x over previous
#include <cuda_runtime.h>
#include <cuda_fp16.h>
#include <cstdint>

#define Bb 8
#define Nn 4096
#define Mm 1024
#define LOG2E 1.4426950408889634f

// ---------------------------------------------------------------------------
// Scratch (device globals) — pre-swizzled images for flat bulk copies
// ---------------------------------------------------------------------------
__device__ __half g_qh[Bb*Nn*64];    // Q hi fp16 (x log2e), per-64-row-chunk images
__device__ __half g_ql[Bb*Nn*64];    // Q lo fp16
__device__ __half g_kh[Bb*Mm*64];    // K hi fp16 ([key][d])
__device__ __half g_kl[Bb*Mm*64];    // K lo fp16
__device__ __half g_qaug[Bb*Nn*24];  // Q-side RBF aug rows (x log2e)
__device__ __half g_kaug[Bb*Mm*24];  // K-side RBF aug rows
__device__ __half g_vT[Bb*Mm*64];    // V^T fp16 images ([d][key])
__device__ __half g_woh[128*128];    // Wo^T hi image
__device__ __half g_wol[128*128];    // Wo^T lo image

#define TH2 (-4.32192809489f)        // log2(0.05)

// ---------------------------------------------------------------------------
// Helpers
// ---------------------------------------------------------------------------
__device__ __forceinline__ uint32_t smem_u32(const void* p) {
    uint32_t a;
    asm("{ .reg .u64 t; cvta.to.shared.u64 t, %1; cvt.u32.u64 %0, t; }" : "=r"(a) : "l"(p));
    return a;
}
__device__ __forceinline__ float ex2f(float x) {
    float y;
    asm("ex2.approx.ftz.f32 %0, %1;" : "=f"(y) : "f"(x));
    return y;
}
__device__ __forceinline__ uint32_t elect_one() {
    uint32_t p;
    asm volatile("{ .reg .pred p; elect.sync _|p, 0xFFFFFFFF; selp.b32 %0,1,0,p; }" : "=r"(p));
    return p;
}

#define MBAR_INIT(a, c) asm volatile("mbarrier.init.shared.b64 [%0], %1;" :: "r"(a), "r"((uint32_t)(c)) : "memory")
#define MBAR_EXPECT(a, b) asm volatile("mbarrier.arrive.expect_tx.shared.b64 _, [%0], %1;" :: "r"(a), "r"((uint32_t)(b)) : "memory")
#define MBAR_ARRIVE(a) asm volatile("mbarrier.arrive.shared.b64 _, [%0];" :: "r"(a) : "memory")
#define MBAR_WAIT(a, ph) do { \
    asm volatile("{ .reg .pred P1; WL_%=: mbarrier.try_wait.parity.acquire.cta.shared::cta.b64 P1, [%0], %1, 0x989680; @P1 bra.uni WD_%=; bra.uni WL_%=; WD_%=: }" \
        :: "r"(a), "r"((uint32_t)(ph)) : "memory"); } while (0)

__device__ __forceinline__ void bulk_cp(uint32_t dst, const void* src, uint32_t bytes, uint32_t mbar) {
    asm volatile("cp.async.bulk.shared::cta.global.mbarrier::complete_tx::bytes [%0], [%1], %2, [%3];"
        :: "r"(dst), "l"(src), "r"(bytes), "r"(mbar) : "memory");
}

__device__ __forceinline__ void ldsm4(uint32_t r[4], uint32_t a) {
    asm volatile("ldmatrix.sync.aligned.m8n8.x4.shared.b16 {%0,%1,%2,%3}, [%4];"
        : "=r"(r[0]), "=r"(r[1]), "=r"(r[2]), "=r"(r[3]) : "r"(a));
}

__device__ __forceinline__ void mma_f16(float c[4], const uint32_t a[4], const uint32_t b[2]) {
    asm volatile("mma.sync.aligned.m16n8k16.row.col.f32.f16.f16.f32 "
        "{%0,%1,%2,%3}, {%4,%5,%6,%7}, {%8,%9}, {%0,%1,%2,%3};"
        : "+f"(c[0]), "+f"(c[1]), "+f"(c[2]), "+f"(c[3])
        : "r"(a[0]), "r"(a[1]), "r"(a[2]), "r"(a[3]), "r"(b[0]), "r"(b[1]));
}

// ---------------------------------------------------------------------------
// prep_proj: ONE wide launch (944 blocks). (UNCHANGED from R14)
// ---------------------------------------------------------------------------
#define PA_H 0u
#define PA_L 8192u
#define PW_H 16384u
#define PW_L 24576u

__global__ __launch_bounds__(256) void prep_proj_kernel(
    const float* __restrict__ xyz1, const float* __restrict__ xyz2,
    const float* __restrict__ gammap,
    const float* __restrict__ p1, const float* __restrict__ p2,
    const float* __restrict__ Wq, const float* __restrict__ Wk,
    const float* __restrict__ Wv, const float* __restrict__ Wo)
{
    __shared__ __align__(16) char sm[32768];
    int bx = blockIdx.x;
    int tid = threadIdx.x;

    if (bx >= 928) {
        int base = (bx - 928) * 1024;
#pragma unroll
        for (int it = 0; it < 4; it++) {
            int i = base + tid + 256*it;
            int k = i >> 7, c = i & 127;
            float w = Wo[i];
            __half h = __float2half_rn(w);
            __half l = __float2half_rn(w - __half2float(h));
            uint32_t sw = ((uint32_t)(k >> 3)) ^ (uint32_t)(c & 7);
            uint32_t off = (uint32_t)c*128u + sw*8u + (uint32_t)(k & 7);
            g_woh[off] = h; g_wol[off] = l;
        }
        return;
    }
    if (bx >= 768) {
        int gr = (bx - 768) * 256 + tid;
        float g = gammap[0];
        float v[5];
        __half* dst;
        bool qside = gr < Bb*Nn;
        if (qside) {
            int b = gr >> 12, n = gr & (Nn-1);
            const float* xp = xyz1 + (size_t)gr*3;
            float x = xp[0], y = xp[1], z = xp[2];
            float gl = g * LOG2E;
            v[0] = 2.0f*gl*x; v[1] = 2.0f*gl*y; v[2] = 2.0f*gl*z;
            v[3] = -gl*(x*x + y*y + z*z); v[4] = LOG2E;
            int img = b*64 + (n >> 6), rr = n & 63;
            dst = g_qaug + (size_t)img*1536 + rr*24;
        } else {
            int gr2 = gr - Bb*Nn;
            if (gr2 >= Bb*Mm) return;
            int b = gr2 >> 10, m = gr2 & (Mm-1);
            const float* xp = xyz2 + (size_t)gr2*3;
            float x = xp[0], y = xp[1], z = xp[2];
            v[0] = x; v[1] = y; v[2] = z;
            v[3] = 1.0f; v[4] = -g*(x*x + y*y + z*z);
            int img = b*16 + (m >> 6), rr = m & 63;
            dst = g_kaug + (size_t)img*1536 + rr*24;
        }
        __half h[5], l[5];
#pragma unroll
        for (int i = 0; i < 5; i++) {
            h[i] = __float2half_rn(v[i]);
            l[i] = __float2half_rn(v[i] - __half2float(h[i]));
        }
        __half row[24];
#pragma unroll
        for (int i = 0; i < 24; i++) row[i] = __float2half_rn(0.0f);
#pragma unroll
        for (int i = 0; i < 5; i++) {
            row[i] = h[i];
            if (qside) { row[5+i] = l[i]; row[10+i] = h[i]; }
            else       { row[5+i] = h[i]; row[10+i] = l[i]; }
        }
        float4* d4 = (float4*)dst;
        const float4* s4 = (const float4*)row;
        d4[0] = s4[0]; d4[1] = s4[1]; d4[2] = s4[2];
        return;
    }

    uint32_t sb = smem_u32(sm);
    int lane = tid & 31, wid = tid >> 5;
    int wm = wid & 3, wn = wid >> 2;

    int mode, rowbase;
    const float *A, *W;
    if (bx < 512)      { mode = 0; A = p1; W = Wq; rowbase = bx*64; }
    else if (bx < 640) { mode = 1; A = p2; W = Wk; rowbase = (bx-512)*64; }
    else               { mode = 2; A = p2; W = Wv; rowbase = (bx-640)*64; }

#pragma unroll
    for (int i = 0; i < 4; i++) {
        int lin = tid + 256*i;
        int r = lin >> 4;
        int k = (lin & 15) * 4;
        float4 v = *(const float4*)(A + (size_t)(rowbase + r)*64 + k);
        __half h[4], l[4];
        h[0]=__float2half_rn(v.x); l[0]=__float2half_rn(v.x-__half2float(h[0]));
        h[1]=__float2half_rn(v.y); l[1]=__float2half_rn(v.y-__half2float(h[1]));
        h[2]=__float2half_rn(v.z); l[2]=__float2half_rn(v.z-__half2float(h[2]));
        h[3]=__float2half_rn(v.w); l[3]=__float2half_rn(v.w-__half2float(h[3]));
        uint32_t off = (uint32_t)r*64u + ((((uint32_t)k >> 3) ^ (uint32_t)(r & 7)) << 3) + (uint32_t)(k & 7);
        *(__half2*)(sm + PA_H + off*2)     = __halves2half2(h[0], h[1]);
        *(__half2*)(sm + PA_H + off*2 + 4) = __halves2half2(h[2], h[3]);
        *(__half2*)(sm + PA_L + off*2)     = __halves2half2(l[0], l[1]);
        *(__half2*)(sm + PA_L + off*2 + 4) = __halves2half2(l[2], l[3]);
    }
#pragma unroll
    for (int it = 0; it < 16; it++) {
        int i = tid + 256*it;
        int k = i >> 6, n = i & 63;
        float w = W[i];
        __half h = __float2half_rn(w);
        __half l = __float2half_rn(w - __half2float(h));
        uint32_t off = (uint32_t)n*64u + ((((uint32_t)k >> 3) ^ (uint32_t)(n & 7)) << 3) + (uint32_t)(k & 7);
        *(__half*)(sm + PW_H + off*2) = h;
        *(__half*)(sm + PW_L + off*2) = l;
    }
    __syncthreads();

    uint32_t frowA = (uint32_t)((lane & 7) + (((lane >> 3) & 1) << 3));
    uint32_t fchkA = (uint32_t)(lane >> 4);
    uint32_t frowB = (uint32_t)((lane & 7) + ((lane >> 4) << 3));
    uint32_t fchkB = (uint32_t)((lane >> 3) & 1);
    uint32_t fsw   = (uint32_t)(lane & 7);

    uint32_t arow = (uint32_t)(wm*16) + frowA;
    uint32_t brow0 = (uint32_t)(wn*32) + frowB;

    float acc[4][4] = {};
#pragma unroll
    for (int s = 0; s < 4; s++) {
        uint32_t chA = ((uint32_t)(2*s) + fchkA) ^ fsw;
        uint32_t chB = ((uint32_t)(2*s) + fchkB) ^ fsw;
        uint32_t ah[4], al[4], bh[2][4], bl[2][4];
        ldsm4(ah, sb + PA_H + arow*128u + (chA << 4));
        ldsm4(al, sb + PA_L + arow*128u + (chA << 4));
        ldsm4(bh[0], sb + PW_H + brow0*128u + (chB << 4));
        ldsm4(bh[1], sb + PW_H + (brow0 + 16u)*128u + (chB << 4));
        ldsm4(bl[0], sb + PW_L + brow0*128u + (chB << 4));
        ldsm4(bl[1], sb + PW_L + (brow0 + 16u)*128u + (chB << 4));
#pragma unroll
        for (int fn = 0; fn < 4; fn++) {
            mma_f16(acc[fn], ah, &bh[fn>>1][2*(fn&1)]);
            mma_f16(acc[fn], al, &bh[fn>>1][2*(fn&1)]);
            mma_f16(acc[fn], ah, &bl[fn>>1][2*(fn&1)]);
        }
    }
    __syncthreads();

    int jj = lane & 3;
    int r0 = wm*16 + (lane >> 2);
    if (mode <= 1) {
        float scl = (mode == 0) ? LOG2E : 1.0f;
#pragma unroll
        for (int fn = 0; fn < 4; fn++) {
            int col = wn*32 + fn*8 + 2*jj;
#pragma unroll
            for (int hh = 0; hh < 2; hh++) {
                int r = r0 + 8*hh;
                float c0 = acc[fn][2*hh+0]*scl, c1 = acc[fn][2*hh+1]*scl;
                __half h0 = __float2half_rn(c0), h1 = __float2half_rn(c1);
                __half l0 = __float2half_rn(c0 - __half2float(h0));
                __half l1 = __float2half_rn(c1 - __half2float(h1));
                uint32_t off = (uint32_t)r*64u + ((((uint32_t)col >> 3) ^ (uint32_t)(r & 7)) << 3) + (uint32_t)(col & 7);
                *(__half2*)(sm + off*2)         = __halves2half2(h0, h1);
                *(__half2*)(sm + 8192 + off*2)  = __halves2half2(l0, l1);
            }
        }
        __syncthreads();
        int img = (mode == 0) ? bx : bx - 512;
        __half* dh = (mode == 0 ? g_qh : g_kh) + (size_t)img*4096;
        __half* dl = (mode == 0 ? g_ql : g_kl) + (size_t)img*4096;
#pragma unroll
        for (int i = 0; i < 2; i++) {
            int lin = tid + 256*i;
            *(uint4*)((char*)dh + lin*16) = *(const uint4*)(sm + lin*16);
            *(uint4*)((char*)dl + lin*16) = *(const uint4*)(sm + 8192 + lin*16);
        }
    } else {
        __half* st = (__half*)sm;
#pragma unroll
        for (int fn = 0; fn < 4; fn++) {
            int col = wn*32 + fn*8 + 2*jj;
#pragma unroll
            for (int hh = 0; hh < 2; hh++) {
                int kk = r0 + 8*hh;
#pragma unroll
                for (int j = 0; j < 2; j++) {
                    int e = col + j;
                    uint32_t off = (uint32_t)e*64u + ((((uint32_t)kk >> 3) ^ (uint32_t)(e & 7)) << 3) + (uint32_t)(kk & 7);
                    st[off] = __float2half_rn(acc[fn][2*hh+j]);
                }
            }
        }
        __syncthreads();
        __half* dv = g_vT + (size_t)(bx - 640)*4096;
#pragma unroll
        for (int i = 0; i < 2; i++) {
            int lin = tid + 256*i;
            *(uint4*)((char*)dv + lin*16) = *(const uint4*)(sm + lin*16);
        }
    }
}

// ---------------------------------------------------------------------------
// Fused attention + OUTPUT MLP. R14 mainloop (2-stage) with:
//  - unconditional flash rescale (no ballot)
//  - persistent Wo^T hi image at TL_BH (74752..107520), loaded once
//  - RED at 40960 inside the BL region (BL copied AFTER combine)
// ---------------------------------------------------------------------------
#define SM_QH     0u
#define SM_QL     8192u
#define SM_QAUG   16384u
#define SM_BUF0   19456u
#define BUF_KH    0u
#define BUF_KL    8192u
#define BUF_KAUG  16384u
#define BUF_V     19456u
#define BUF_BYTES 27648u
#define SM_BUF1   (SM_BUF0 + BUF_BYTES)
#define RED_STRIDE 68
#define TL_AH   0u
#define TL_AL   16384u
#define TL_BL   32768u       // 32768..65536
#define TL_RED  40960u       // 40960..58368, inside BL (BL copied after combine)
#define TL_BH   74752u       // persistent Wo^T hi (mainloop tops out at 74752)
#define SM_TOTAL 107520

__global__ __launch_bounds__(256, 2) void attn_mma_kernel(
    const float* __restrict__ p1, const float* __restrict__ bo,
    float* __restrict__ out)
{
    extern __shared__ char dyn[];
    __shared__ __align__(8) uint64_t mbars[4];   // full0, full1, free0, free1
    __shared__ float sDen[2][64];
    __shared__ float sM[2][64];

    uint32_t sb = smem_u32(dyn);
    int tid = threadIdx.x, lane = tid & 31, wid = tid >> 5;
    int wm = wid & 3, wn = wid >> 2;
    int bI = blockIdx.y, nbase = blockIdx.x * 64;

    uint32_t mb[2] = { smem_u32(&mbars[0]), smem_u32(&mbars[1]) };
    uint32_t fr[2] = { smem_u32(&mbars[2]), smem_u32(&mbars[3]) };
    if (tid == 0) {
        MBAR_INIT(mb[0], 1); MBAR_INIT(mb[1], 1);
        MBAR_INIT(fr[0], 8); MBAR_INIT(fr[1], 8);
    }
    __syncthreads();

    if (tid == 0) {
        int img = bI * 16;
        int qimg = bI*64 + blockIdx.x;
        MBAR_EXPECT(mb[0], 8192u*2 + 3072u + 32768u + BUF_BYTES);
        bulk_cp(sb + SM_QH,   g_qh   + (size_t)qimg*4096, 8192, mb[0]);
        bulk_cp(sb + SM_QL,   g_ql   + (size_t)qimg*4096, 8192, mb[0]);
        bulk_cp(sb + SM_QAUG, g_qaug + (size_t)qimg*1536, 3072, mb[0]);
        bulk_cp(sb + TL_BH,   g_woh, 32768, mb[0]);
        bulk_cp(sb + SM_BUF0 + BUF_KH,   g_kh   + (size_t)img*4096, 8192, mb[0]);
        bulk_cp(sb + SM_BUF0 + BUF_KL,   g_kl   + (size_t)img*4096, 8192, mb[0]);
        bulk_cp(sb + SM_BUF0 + BUF_KAUG, g_kaug + (size_t)img*1536, 3072, mb[0]);
        bulk_cp(sb + SM_BUF0 + BUF_V,    g_vT   + (size_t)img*4096, 8192, mb[0]);
        MBAR_EXPECT(mb[1], BUF_BYTES);
        bulk_cp(sb + SM_BUF1 + BUF_KH,   g_kh   + (size_t)(img+1)*4096, 8192, mb[1]);
        bulk_cp(sb + SM_BUF1 + BUF_KL,   g_kl   + (size_t)(img+1)*4096, 8192, mb[1]);
        bulk_cp(sb + SM_BUF1 + BUF_KAUG, g_kaug + (size_t)(img+1)*1536, 3072, mb[1]);
        bulk_cp(sb + SM_BUF1 + BUF_V,    g_vT   + (size_t)(img+1)*4096, 8192, mb[1]);
    }

    uint32_t frowA = (uint32_t)((lane & 7) + (((lane >> 3) & 1) << 3));
    uint32_t fchkA = (uint32_t)(lane >> 4);
    uint32_t frowB = (uint32_t)((lane & 7) + ((lane >> 4) << 3));
    uint32_t fchkB = (uint32_t)((lane >> 3) & 1);
    uint32_t fsw   = (uint32_t)(lane & 7);
    int jj = lane & 3;

    MBAR_WAIT(mb[0], 0);
    uint32_t qaug[4];
    ldsm4(qaug, sb + SM_QAUG + ((uint32_t)(wm*16) + frowA)*48u + fchkA*16u);

    float oaccT[4][2][4] = {};
    float dsum[2] = {};
    float mold[2] = { -30000.0f, -30000.0f };

    uint32_t qrow = (uint32_t)(wm*16) + frowA;
    uint32_t krow0 = (uint32_t)(wn*32) + frowB;

    for (int t = 0; t < 16; t++) {
        int idx = t & 1;
        uint32_t bufb = sb + (idx ? SM_BUF1 : SM_BUF0);
        if (t) MBAR_WAIT(mb[idx], (t >> 1) & 1);

        // ---- MMA1: S' (log2 domain, 3-pass fp16) + R' (aug) ----
        float sacc[4][4] = {};
        float racc[4][4] = {};
#pragma unroll
        for (int s = 0; s < 4; s++) {
            uint32_t chA = ((uint32_t)(2*s) + fchkA) ^ fsw;
            uint32_t chB = ((uint32_t)(2*s) + fchkB) ^ fsw;
            uint32_t qh_f[4], ql_f[4], kh2[2][4], kl2[2][4];
            ldsm4(qh_f, sb + SM_QH + qrow*128u + (chA << 4));
            ldsm4(ql_f, sb + SM_QL + qrow*128u + (chA << 4));
            ldsm4(kh2[0], bufb + BUF_KH + krow0*128u + (chB << 4));
            ldsm4(kh2[1], bufb + BUF_KH + (krow0 + 16u)*128u + (chB << 4));
            ldsm4(kl2[0], bufb + BUF_KL + krow0*128u + (chB << 4));
            ldsm4(kl2[1], bufb + BUF_KL + (krow0 + 16u)*128u + (chB << 4));
#pragma unroll
            for (int fn = 0; fn < 4; fn++) {
                mma_f16(sacc[fn], qh_f, &kh2[fn>>1][2*(fn&1)]);
                mma_f16(sacc[fn], qh_f, &kl2[fn>>1][2*(fn&1)]);
                mma_f16(sacc[fn], ql_f, &kh2[fn>>1][2*(fn&1)]);
            }
        }
        {
            uint32_t ka[2][4];
            ldsm4(ka[0], bufb + BUF_KAUG + krow0*48u + fchkB*16u);
            ldsm4(ka[1], bufb + BUF_KAUG + (krow0 + 16u)*48u + fchkB*16u);
#pragma unroll
            for (int fn = 0; fn < 4; fn++)
                mma_f16(racc[fn], qaug, &ka[fn>>1][2*(fn&1)]);
        }

        // ---- flash row-max update (log2 units), unconditional rescale ----
        float mt0 = sacc[0][0], mt1 = sacc[0][2];
#pragma unroll
        for (int fn = 0; fn < 4; fn++) {
            mt0 = fmaxf(mt0, fmaxf(sacc[fn][0], sacc[fn][1]));
            mt1 = fmaxf(mt1, fmaxf(sacc[fn][2], sacc[fn][3]));
        }
        mt0 = fmaxf(mt0, __shfl_xor_sync(0xFFFFFFFFu, mt0, 1));
        mt0 = fmaxf(mt0, __shfl_xor_sync(0xFFFFFFFFu, mt0, 2));
        mt1 = fmaxf(mt1, __shfl_xor_sync(0xFFFFFFFFu, mt1, 1));
        mt1 = fmaxf(mt1, __shfl_xor_sync(0xFFFFFFFFu, mt1, 2));
        float mn0 = fmaxf(mold[0], mt0);
        float mn1 = fmaxf(mold[1], mt1);
        {
            float f0 = ex2f(mold[0] - mn0);
            float f1 = ex2f(mold[1] - mn1);
            dsum[0] *= f0; dsum[1] *= f1;
            float fq0 = __shfl_sync(0xFFFFFFFFu, f0, 8*jj);
            float fq1 = __shfl_sync(0xFFFFFFFFu, f0, 8*jj + 4);
            float fq2 = __shfl_sync(0xFFFFFFFFu, f1, 8*jj);
            float fq3 = __shfl_sync(0xFFFFFFFFu, f1, 8*jj + 4);
#pragma unroll
            for (int g = 0; g < 4; g++) {
                oaccT[g][0][0] *= fq0; oaccT[g][0][1] *= fq1;
                oaccT[g][0][2] *= fq0; oaccT[g][0][3] *= fq1;
                oaccT[g][1][0] *= fq2; oaccT[g][1][1] *= fq3;
                oaccT[g][1][2] *= fq2; oaccT[g][1][3] *= fq3;
            }
        }
        mold[0] = mn0; mold[1] = mn1;

        // ---- epilogue: e2 = 2^(s'-m'), u = 2^(r') predicated, pv = e2*u ----
        uint32_t bq[2][2][2];
#pragma unroll
        for (int kc = 0; kc < 2; kc++) {
#pragma unroll
            for (int fo = 0; fo < 2; fo++) {
                int fn = 2*kc + fo;
                float pvf[4];
#pragma unroll
                for (int e = 0; e < 4; e++) {
                    float s = sacc[fn][e];
                    float m = (e < 2) ? mn0 : mn1;
                    float e2 = ex2f(s - m);
                    if (e < 2) dsum[0] += e2; else dsum[1] += e2;
                    float r = racc[fn][e];
                    float u = 0.0f;
                    if (r > TH2) u = ex2f(r);
                    pvf[e] = e2 * u;
                }
                __half2 p01 = __floats2half2_rn(pvf[0], pvf[1]);
                __half2 p23 = __floats2half2_rn(pvf[2], pvf[3]);
                bq[kc][0][fo] = *(uint32_t*)&p01;
                bq[kc][1][fo] = *(uint32_t*)&p23;
            }
        }

        // ---- MMA2: O^T += V^T x P^T (fp16) ----
#pragma unroll
        for (int kc = 0; kc < 2; kc++) {
            uint32_t chV = ((uint32_t)(wn*4 + 2*kc) + fchkA) ^ fsw;
#pragma unroll
            for (int g = 0; g < 4; g++) {
                uint32_t vfr[4];
                ldsm4(vfr, bufb + BUF_V + ((uint32_t)(16*g) + frowA)*128u + (chV << 4));
                mma_f16(oaccT[g][0], vfr, bq[kc][0]);
                mma_f16(oaccT[g][1], vfr, bq[kc][1]);
            }
        }

        if (elect_one()) MBAR_ARRIVE(fr[idx]);

        if (t < 14 && tid == 0) {
            MBAR_WAIT(fr[idx], (t >> 1) & 1);
            int img = bI*16 + t + 2;
            uint32_t dstb = sb + (idx ? SM_BUF1 : SM_BUF0);
            MBAR_EXPECT(mb[idx], BUF_BYTES);
            bulk_cp(dstb + BUF_KH,   g_kh   + (size_t)img*4096, 8192, mb[idx]);
            bulk_cp(dstb + BUF_KL,   g_kl   + (size_t)img*4096, 8192, mb[idx]);
            bulk_cp(dstb + BUF_KAUG, g_kaug + (size_t)img*1536, 3072, mb[idx]);
            bulk_cp(dstb + BUF_V,    g_vT   + (size_t)img*4096, 8192, mb[idx]);
        }
    }

    __syncthreads();

    // =======================  TAIL: combine + fused MLP  ====================

#pragma unroll
    for (int off = 1; off < 4; off <<= 1)
#pragma unroll
        for (int h = 0; h < 2; h++)
            dsum[h] += __shfl_xor_sync(0xFFFFFFFFu, dsum[h], off);
    int rloc = lane >> 2;
    if (jj == 0) {
#pragma unroll
        for (int h = 0; h < 2; h++) {
            sDen[wn][wm*16 + rloc + 8*h] = dsum[h];
            sM[wn][wm*16 + rloc + 8*h]   = mold[h];
        }
    }

    float* sRed = (float*)(dyn + TL_RED);
    if (wn == 1) {
#pragma unroll
        for (int g = 0; g < 4; g++)
#pragma unroll
            for (int qb = 0; qb < 2; qb++) {
                int q0 = wm*16 + qb*8 + 2*jj;
                int d0 = 16*g + rloc;
                sRed[(q0+0)*RED_STRIDE + d0]     = oaccT[g][qb][0];
                sRed[(q0+1)*RED_STRIDE + d0]     = oaccT[g][qb][1];
                sRed[(q0+0)*RED_STRIDE + d0 + 8] = oaccT[g][qb][2];
                sRed[(q0+1)*RED_STRIDE + d0 + 8] = oaccT[g][qb][3];
            }
    }

    // A image p1-half (all warps)
    {
        const float* p1base = p1 + ((size_t)bI*Nn + nbase)*64;
#pragma unroll
        for (int i = 0; i < 4; i++) {
            int lin = tid + 256*i;
            int r = lin >> 4;
            int k = (lin & 15) * 4;
            float4 v = *(const float4*)(p1base + (size_t)r*64 + k);
            __half h[4], l[4];
            h[0]=__float2half_rn(v.x); l[0]=__float2half_rn(v.x-__half2float(h[0]));
            h[1]=__float2half_rn(v.y); l[1]=__float2half_rn(v.y-__half2float(h[1]));
            h[2]=__float2half_rn(v.z); l[2]=__float2half_rn(v.z-__half2float(h[2]));
            h[3]=__float2half_rn(v.w); l[3]=__float2half_rn(v.w-__half2float(h[3]));
            uint32_t sw = ((uint32_t)(k >> 3)) ^ (uint32_t)(r & 7);
            uint32_t off = (uint32_t)r*128u + sw*8u + (uint32_t)(k & 7);
            *(__half2*)(dyn + TL_AH + off*2)     = __halves2half2(h[0], h[1]);
            *(__half2*)(dyn + TL_AH + off*2 + 4) = __halves2half2(h[2], h[3]);
            *(__half2*)(dyn + TL_AL + off*2)     = __halves2half2(l[0], l[1]);
            *(__half2*)(dyn + TL_AL + off*2 + 4) = __halves2half2(l[2], l[3]);
        }
    }
    __syncthreads();

    // wn==0: combine halves (log2-domain maxes), write kern cols 64..127
    if (wn == 0) {
        float ca[2][2], cb[2][2];
#pragma unroll
        for (int qb = 0; qb < 2; qb++)
#pragma unroll
            for (int par2 = 0; par2 < 2; par2++) {
                int rg = wm*16 + qb*8 + 2*jj + par2;
                float m0 = sM[0][rg], m1 = sM[1][rg];
                float Mx = fmaxf(m0, m1);
                float e0 = ex2f(m0 - Mx), e1 = ex2f(m1 - Mx);
                float den = sDen[0][rg]*e0 + sDen[1][rg]*e1;
                float inv = 1.0f / den;
                ca[qb][par2] = e0 * inv;
                cb[qb][par2] = e1 * inv;
            }
#pragma unroll
        for (int g = 0; g < 4; g++)
#pragma unroll
            for (int qb = 0; qb < 2; qb++) {
                int q0 = wm*16 + qb*8 + 2*jj;
                int d0 = 16*g + rloc;
#pragma unroll
                for (int e = 0; e < 4; e++) {
                    int par2 = e & 1;
                    int r = q0 + par2;
                    int d = d0 + 8*(e >> 1);
                    float val = oaccT[g][qb][e]*ca[qb][par2]
                              + sRed[r*RED_STRIDE + d]*cb[qb][par2];
                    int k = 64 + d;
                    __half h = __float2half_rn(val);
                    __half l = __float2half_rn(val - __half2float(h));
                    uint32_t sw = ((uint32_t)(k >> 3)) ^ (uint32_t)(r & 7);
                    uint32_t off = (uint32_t)r*128u + sw*8u + (uint32_t)(k & 7);
                    *(__half*)(dyn + TL_AH + off*2) = h;
                    *(__half*)(dyn + TL_AL + off*2) = l;
                }
            }
    }
    __syncthreads();

    // Wo^T lo copy (overwrites RED — dead now)
#pragma unroll
    for (int i = 0; i < 8; i++) {
        int lin = tid + 256*i;
        *(uint4*)(dyn + TL_BL + lin*16) = *(const uint4*)((const char*)g_wol + lin*16);
    }
    __syncthreads();

    // merged single-pass MLP: ah*bh + al*bh + ah*bl  (bh persistent @ TL_BH)
    uint32_t arow = (uint32_t)(wm*16) + frowA;
    uint32_t brow0 = (uint32_t)(wn*64) + frowB;
    float macc[8][4] = {};
#pragma unroll
    for (int s = 0; s < 8; s++) {
        uint32_t chA = ((uint32_t)(2*s) + fchkA) ^ fsw;
        uint32_t chB = ((uint32_t)(2*s) + fchkB) ^ fsw;
        uint32_t ah[4], al[4], bh[4][4], bl[4][4];
        ldsm4(ah, sb + TL_AH + arow*256u + (chA << 4));
        ldsm4(al, sb + TL_AL + arow*256u + (chA << 4));
#pragma unroll
        for (int g = 0; g < 4; g++) {
            ldsm4(bh[g], sb + TL_BH + (brow0 + 16u*g)*256u + (chB << 4));
            ldsm4(bl[g], sb + TL_BL + (brow0 + 16u*g)*256u + (chB << 4));
        }
#pragma unroll
        for (int fn = 0; fn < 8; fn++) {
            mma_f16(macc[fn], ah, &bh[fn>>1][2*(fn&1)]);
            mma_f16(macc[fn], al, &bh[fn>>1][2*(fn&1)]);
            mma_f16(macc[fn], ah, &bl[fn>>1][2*(fn&1)]);
        }
    }

    // bias + relu + store
#pragma unroll
    for (int fn = 0; fn < 8; fn++) {
        int col = wn*64 + fn*8 + 2*jj;
        float2 bv = *(const float2*)(bo + col);
#pragma unroll
        for (int h = 0; h < 2; h++) {
            int grow = bI*Nn + nbase + wm*16 + rloc + 8*h;
            float2 o;
            o.x = fmaxf(macc[fn][2*h+0] + bv.x, 0.0f);
            o.y = fmaxf(macc[fn][2*h+1] + bv.y, 0.0f);
            *(float2*)(out + (size_t)grow*128 + col) = o;
        }
    }
}

// ---------------------------------------------------------------------------
extern "C" void kernel_launch(void* const* d_in, const int* in_sizes, int n_in,
                              void* d_out, int out_size)
{
    const float* xyz1 = (const float*)d_in[0];
    const float* xyz2 = (const float*)d_in[1];
    const float* p1   = (const float*)d_in[2];
    const float* p2   = (const float*)d_in[3];
    const float* Wq   = (const float*)d_in[4];
    const float* Wk   = (const float*)d_in[5];
    const float* Wv   = (const float*)d_in[6];
    const float* gm   = (const float*)d_in[7];
    const float* Wo   = (const float*)d_in[8];
    const float* bo   = (const float*)d_in[9];
    float* out = (float*)d_out;

    prep_proj_kernel<<<944, 256>>>(xyz1, xyz2, gm, p1, p2, Wq, Wk, Wv, Wo);

    cudaFuncSetAttribute(attn_mma_kernel, cudaFuncAttributeMaxDynamicSharedMemorySize, SM_TOTAL);
    attn_mma_kernel<<<dim3(Nn/64, Bb), 256, SM_TOTAL>>>(p1, bo, out);
}